// round 14
// baseline (speedup 1.0000x reference)
#include <cuda_runtime.h>

#define SIZE 512
#define NS 256
#define NT 128
#define NTILES 8192
#define KST4 132     // per-warp keep stride in float4 (264 float2 >= 256+4 sentinels)

__device__ int g_tile_counter;

__device__ __forceinline__ float fsqrt_approx(float x) {
    float r; asm("sqrt.approx.f32 %0, %1;" : "=f"(r) : "f"(x)); return r;
}
__device__ __forceinline__ float fexp2_approx(float x) {
    float r; asm("ex2.approx.f32 %0, %1;" : "=f"(r) : "f"(x)); return r;
}
__device__ __forceinline__ float flog2_approx(float x) {
    float r; asm("lg2.approx.f32 %0, %1;" : "=f"(r) : "f"(x)); return r;
}
__device__ __forceinline__ float frcp_approx(float x) {
    float r; asm("rcp.approx.f32 %0, %1;" : "=f"(r) : "f"(x)); return r;
}

// ---- process one 8x4 tile with one warp ----
__device__ __forceinline__ void process_tile(
    int tile, int lane, const float4* __restrict__ samp,
    float2* __restrict__ kp, float* __restrict__ out)
{
    const int x0 = (tile & 63) * 8;
    const int y0 = (tile >> 6) * 4;

    const float inv = 1.0f / 511.0f;
    const float cx = ((float)x0 + 3.5f) * inv;
    const float cy = ((float)y0 + 1.5f) * inv;
    const float R  = 0.0074617f + 1e-4f;     // 0.5*sqrt(7^2+3^2)/511

    // 8 samples per lane: center dist^2 + warp-min (REDUX on float bits, all >=0)
    float2 s[8];
    float  dc2[8];
    float  m = 1e30f;
    #pragma unroll
    for (int j = 0; j < 4; j++) {
        const float4 v = samp[j * 32 + lane];
        s[2 * j]     = make_float2(v.x, v.y);
        s[2 * j + 1] = make_float2(v.z, v.w);
        float ax = cx - v.x, ay = cy - v.y;
        dc2[2 * j] = fmaf(ax, ax, ay * ay);
        ax = cx - v.z; ay = cy - v.w;
        dc2[2 * j + 1] = fmaf(ax, ax, ay * ay);
        m = fminf(m, fminf(dc2[2 * j], dc2[2 * j + 1]));
    }
    const float dcmin =
        sqrtf(__int_as_float(__reduce_min_sync(0xffffffffu, __float_as_int(m))));

    const int px = x0 + (lane & 7);
    const int py = y0 + (lane >> 3);
    const int p  = py * SIZE + px;

    // tile skip: coverage < 1e-4
    if (dcmin > 0.1154f) {
        out[p] = 1.0f;
        return;
    }

    // adaptive keep margin (err <= 1e-4)
    const float delta = fminf(0.0513f,
                        fmaxf(0.0567f - 0.781f * (dcmin - 0.0693f), 0.005f));
    const float thr  = dcmin + 2.0f * R + delta;
    const float thr2 = thr * thr;

    const unsigned lt = (1u << lane) - 1u;
    int c = 0;
    #pragma unroll
    for (int j = 0; j < 8; j++) {
        const bool k = (dc2[j] <= thr2);
        const unsigned msk = __ballot_sync(0xffffffffu, k);
        if (k) kp[c + __popc(msk & lt)] = s[j];
        c += __popc(msk);
    }
    if (lane < 4) kp[c + lane] = make_float2(100.0f, 100.0f);  // sentinels
    __syncwarp();
    const int nIt = ((c + 3) & ~3) >> 1;     // float4 iterations (even count)

    // per-pixel single-pass soft-min, dual accumulators
    const float gx = (float)px * inv;
    const float gy = (float)py * inv;
    const float NEGK = -369.3298503f;        // -256 * log2(e)
    const float4* kp4 = (const float4*)kp;
    float accA = 0.0f, accB = 0.0f;
    #pragma unroll 4
    for (int i = 0; i < nIt; i++) {
        const float4 q = kp4[i];             // broadcast LDS.128
        float ax = gx - q.x, ay = gy - q.y;
        const float dA = fsqrt_approx(fmaf(ax, ax, ay * ay));
        ax = gx - q.z; ay = gy - q.w;
        const float dB = fsqrt_approx(fmaf(ax, ax, ay * ay));
        accA += fexp2_approx(dA * NEGK);
        accB += fexp2_approx(dB * NEGK);
    }

    const float md = flog2_approx(accA + accB) * (-0.69314718f / 256.0f);
    const float z  = (0.04f - md) * (200.0f * 1.44269504f);
    out[p] = frcp_approx(1.0f + fexp2_approx(z));
}

// ---- persistent kernel: 4 warps/CTA, each warp steals tiles dynamically ----
__global__ __launch_bounds__(NT)
void glyph_kernel(const float* __restrict__ cp, float* __restrict__ out)
{
    __shared__ float4 samp[NS / 2];          // 256 samples as 128 float4 pairs
    __shared__ float4 keepbuf[4 * KST4];     // private AoS segment per warp

    const int tid  = threadIdx.x;
    const int lane = tid & 31;
    const int w    = tid >> 5;

    // ---- per-CTA Bezier samples: thread t computes samples 2t and 2t+1 ----
    {
        const float4* cp4 = (const float4*)cp;
        const int stroke = tid >> 4;
        const float4 a = cp4[2 * stroke];
        const float4 b = cp4[2 * stroke + 1];
        const float q0x = __saturatef(a.x), q0y = __saturatef(a.y);
        const float q1x = __saturatef(a.z), q1y = __saturatef(a.w);
        const float q2x = __saturatef(b.x), q2y = __saturatef(b.y);
        const float q3x = __saturatef(b.z), q3y = __saturatef(b.w);
        const int j = (2 * tid) & 31;
        float4 o;
        {
            const float t  = (float)j * (1.0f / 31.0f);
            const float mt = 1.0f - t;
            const float w0 = mt * mt * mt, w1 = 3.0f * mt * mt * t;
            const float w2 = 3.0f * mt * t * t, w3 = t * t * t;
            o.x = w0 * q0x + w1 * q1x + w2 * q2x + w3 * q3x;
            o.y = w0 * q0y + w1 * q1y + w2 * q2y + w3 * q3y;
        }
        {
            const float t  = (float)(j + 1) * (1.0f / 31.0f);
            const float mt = 1.0f - t;
            const float w0 = mt * mt * mt, w1 = 3.0f * mt * mt * t;
            const float w2 = 3.0f * mt * t * t, w3 = t * t * t;
            o.z = w0 * q0x + w1 * q1x + w2 * q2x + w3 * q3x;
            o.w = w0 * q0y + w1 * q1y + w2 * q2y + w3 * q3y;
        }
        samp[tid] = o;
    }
    __syncthreads();
    // warps fully independent from here

    float2* kp = (float2*)(keepbuf + w * KST4);

    // first tile: static (avoids atomic burst at start), then dynamic stealing
    int tile = blockIdx.x * 4 + w;
    while (tile < NTILES) {
        process_tile(tile, lane, samp, kp, out);
        int t;
        if (lane == 0) t = atomicAdd(&g_tile_counter, 1);
        tile = __shfl_sync(0xffffffffu, t, 0);
    }
}

extern "C" void kernel_launch(void* const* d_in, const int* in_sizes, int n_in,
                              void* d_out, int out_size) {
    const float* cp = (const float*)d_in[0];   // control_points [8,4,2]
    float* out = (float*)d_out;

    // zero the work counter to the first dynamically-stolen tile id
    static int first_dynamic = 1480 * 4;       // after the static pre-assignment
    void* ctr_addr = nullptr;
    cudaGetSymbolAddress(&ctr_addr, g_tile_counter);
    cudaMemcpyAsync(ctr_addr, &first_dynamic, sizeof(int),
                    cudaMemcpyHostToDevice, 0);

    glyph_kernel<<<1480, NT>>>(cp, out);       // one wave: 148 SMs x 10 CTAs
}

// round 15
// speedup vs baseline: 1.4244x; 1.4244x over previous
#include <cuda_runtime.h>

#define SIZE 512
#define NS 256
#define NT 128
#define NTILES 8192
#define NCTAS 1184
#define NWARPS (NCTAS * 4)     // 4736; each warp does tiles {g, g+4736}
#define KST4 132               // per-warp keep stride in float4

__device__ __forceinline__ float fsqrt_approx(float x) {
    float r; asm("sqrt.approx.f32 %0, %1;" : "=f"(r) : "f"(x)); return r;
}
__device__ __forceinline__ float fexp2_approx(float x) {
    float r; asm("ex2.approx.f32 %0, %1;" : "=f"(r) : "f"(x)); return r;
}
__device__ __forceinline__ float flog2_approx(float x) {
    float r; asm("lg2.approx.f32 %0, %1;" : "=f"(r) : "f"(x)); return r;
}
__device__ __forceinline__ float frcp_approx(float x) {
    float r; asm("rcp.approx.f32 %0, %1;" : "=f"(r) : "f"(x)); return r;
}

// ---- process one 8x4 tile with one warp (measured-best R12 pipeline) ----
__device__ __forceinline__ void process_tile(
    int tile, int lane, const float4* __restrict__ samp,
    float2* __restrict__ kp, float* __restrict__ out)
{
    const int x0 = (tile & 63) * 8;
    const int y0 = (tile >> 6) * 4;

    const float inv = 1.0f / 511.0f;
    const float cx = ((float)x0 + 3.5f) * inv;
    const float cy = ((float)y0 + 1.5f) * inv;
    const float R  = 0.0074617f + 1e-4f;     // 0.5*sqrt(7^2+3^2)/511

    float2 s[8];
    float  dc2[8];
    float  m = 1e30f;
    #pragma unroll
    for (int j = 0; j < 4; j++) {
        const float4 v = samp[j * 32 + lane];
        s[2 * j]     = make_float2(v.x, v.y);
        s[2 * j + 1] = make_float2(v.z, v.w);
        float ax = cx - v.x, ay = cy - v.y;
        dc2[2 * j] = fmaf(ax, ax, ay * ay);
        ax = cx - v.z; ay = cy - v.w;
        dc2[2 * j + 1] = fmaf(ax, ax, ay * ay);
        m = fminf(m, fminf(dc2[2 * j], dc2[2 * j + 1]));
    }
    const float dcmin =
        sqrtf(__int_as_float(__reduce_min_sync(0xffffffffu, __float_as_int(m))));

    const int px = x0 + (lane & 7);
    const int py = y0 + (lane >> 3);
    const int p  = py * SIZE + px;

    if (dcmin > 0.1154f) {                   // coverage < 1e-4
        out[p] = 1.0f;
        return;
    }

    // adaptive keep margin (output err <= 1e-4)
    const float delta = fminf(0.0513f,
                        fmaxf(0.0567f - 0.781f * (dcmin - 0.0693f), 0.005f));
    const float thr  = dcmin + 2.0f * R + delta;
    const float thr2 = thr * thr;

    const unsigned lt = (1u << lane) - 1u;
    int c = 0;
    #pragma unroll
    for (int j = 0; j < 8; j++) {
        const bool k = (dc2[j] <= thr2);
        const unsigned msk = __ballot_sync(0xffffffffu, k);
        if (k) kp[c + __popc(msk & lt)] = s[j];
        c += __popc(msk);
    }
    if (lane < 4) kp[c + lane] = make_float2(100.0f, 100.0f);  // sentinels
    __syncwarp();
    const int nIt = ((c + 3) & ~3) >> 1;

    const float gx = (float)px * inv;
    const float gy = (float)py * inv;
    const float NEGK = -369.3298503f;        // -256 * log2(e)
    const float4* kp4 = (const float4*)kp;
    float accA = 0.0f, accB = 0.0f;
    #pragma unroll 4
    for (int i = 0; i < nIt; i++) {
        const float4 q = kp4[i];
        float ax = gx - q.x, ay = gy - q.y;
        const float dA = fsqrt_approx(fmaf(ax, ax, ay * ay));
        ax = gx - q.z; ay = gy - q.w;
        const float dB = fsqrt_approx(fmaf(ax, ax, ay * ay));
        accA += fexp2_approx(dA * NEGK);
        accB += fexp2_approx(dB * NEGK);
    }

    const float md = flog2_approx(accA + accB) * (-0.69314718f / 256.0f);
    const float z  = (0.04f - md) * (200.0f * 1.44269504f);
    out[p] = frcp_approx(1.0f + fexp2_approx(z));
}

// ---- single-wave kernel: 4 warps/CTA, 2 strided tiles per warp, no atomics ----
__global__ __launch_bounds__(NT)
void glyph_kernel(const float* __restrict__ cp, float* __restrict__ out)
{
    __shared__ float4 samp[NS / 2];
    __shared__ float4 keepbuf[4 * KST4];

    const int tid  = threadIdx.x;
    const int lane = tid & 31;
    const int w    = tid >> 5;

    // per-CTA Bezier samples: thread t computes samples 2t and 2t+1
    {
        const float4* cp4 = (const float4*)cp;
        const int stroke = tid >> 4;
        const float4 a = cp4[2 * stroke];
        const float4 b = cp4[2 * stroke + 1];
        const float q0x = __saturatef(a.x), q0y = __saturatef(a.y);
        const float q1x = __saturatef(a.z), q1y = __saturatef(a.w);
        const float q2x = __saturatef(b.x), q2y = __saturatef(b.y);
        const float q3x = __saturatef(b.z), q3y = __saturatef(b.w);
        const int j = (2 * tid) & 31;
        float4 o;
        {
            const float t  = (float)j * (1.0f / 31.0f);
            const float mt = 1.0f - t;
            const float w0 = mt * mt * mt, w1 = 3.0f * mt * mt * t;
            const float w2 = 3.0f * mt * t * t, w3 = t * t * t;
            o.x = w0 * q0x + w1 * q1x + w2 * q2x + w3 * q3x;
            o.y = w0 * q0y + w1 * q1y + w2 * q2y + w3 * q3y;
        }
        {
            const float t  = (float)(j + 1) * (1.0f / 31.0f);
            const float mt = 1.0f - t;
            const float w0 = mt * mt * mt, w1 = 3.0f * mt * mt * t;
            const float w2 = 3.0f * mt * t * t, w3 = t * t * t;
            o.z = w0 * q0x + w1 * q1x + w2 * q2x + w3 * q3x;
            o.w = w0 * q0y + w1 * q1y + w2 * q2y + w3 * q3y;
        }
        samp[tid] = o;
    }
    __syncthreads();
    // warps fully independent from here

    float2* kp = (float2*)(keepbuf + w * KST4);
    const int g = blockIdx.x * 4 + w;          // global warp id, 0..4735

    process_tile(g, lane, samp, kp, out);
    const int t2 = g + NWARPS;                 // 74 rows away: decorrelated load
    if (t2 < NTILES)
        process_tile(t2, lane, samp, kp, out);
}

extern "C" void kernel_launch(void* const* d_in, const int* in_sizes, int n_in,
                              void* d_out, int out_size) {
    const float* cp = (const float*)d_in[0];   // control_points [8,4,2]
    float* out = (float*)d_out;
    glyph_kernel<<<NCTAS, NT>>>(cp, out);      // 1184 CTAs = 8/SM, one wave
}